// round 1
// baseline (speedup 1.0000x reference)
#include <cuda_runtime.h>

#define NN 50000
#define TT 1000
#define NCL 5
#define TWO_PI_F 6.28318530717958647692f

// ---------------- device scratch (no allocations allowed) ----------------
__device__ float  g_stats[NCL * 13];        // per cluster: [0]=cnt, [1..4]=amp sums, [5..8]=cos sums, [9..12]=sin sums
__device__ float  g_cmean_amp[NCL * 4];
__device__ float  g_cmean_ph[NCL * 4];
__device__ float  g_ccnt[NCL];
__device__ float4 g_cosph[NN];
__device__ float4 g_sinph[NN];
__device__ float  g_coeff[NN * 12];         // per row: off, trend, (acos,asin) x4, pad2  (48B aligned)
__device__ float  g_basis[10 * 1024];       // row j = basis_j over t (stride 1024 floats)

// ---------------- f32x2 helpers ----------------
__device__ __forceinline__ unsigned long long f32x2_fma(unsigned long long a,
                                                        unsigned long long b,
                                                        unsigned long long c) {
    unsigned long long d;
    asm("fma.rn.f32x2 %0, %1, %2, %3;" : "=l"(d) : "l"(a), "l"(b), "l"(c));
    return d;
}
__device__ __forceinline__ unsigned long long pk2(float lo, float hi) {
    unsigned long long d;
    asm("mov.b64 %0, {%1, %2};" : "=l"(d) : "r"(__float_as_uint(lo)), "r"(__float_as_uint(hi)));
    return d;
}

// ---------------- kernel 1: zero cluster stats ----------------
__global__ void k_zero() {
    int i = threadIdx.x;
    if (i < NCL * 13) g_stats[i] = 0.f;
}

// ---------------- kernel 2: sincos of raw phases + cluster partial sums ----------------
__global__ void k_accum(const float4* __restrict__ amp4, const float4* __restrict__ ph4,
                        const int* __restrict__ labels) {
    __shared__ float sh[NCL * 13];
    int tid = threadIdx.x;
    if (tid < NCL * 13) sh[tid] = 0.f;
    __syncthreads();
    int n = blockIdx.x * blockDim.x + tid;
    if (n < NN) {
        float4 a = amp4[n];
        float4 p = ph4[n];
        float cx, sx, cy, sy, cz, sz, cw, sw;
        sincosf(p.x, &sx, &cx);
        sincosf(p.y, &sy, &cy);
        sincosf(p.z, &sz, &cz);
        sincosf(p.w, &sw, &cw);
        g_cosph[n] = make_float4(cx, cy, cz, cw);
        g_sinph[n] = make_float4(sx, sy, sz, sw);
        int l = labels[n];
        float* b = &sh[l * 13];
        atomicAdd(&b[0], 1.f);
        atomicAdd(&b[1], a.x);  atomicAdd(&b[2], a.y);  atomicAdd(&b[3], a.z);  atomicAdd(&b[4], a.w);
        atomicAdd(&b[5], cx);   atomicAdd(&b[6], cy);   atomicAdd(&b[7], cz);   atomicAdd(&b[8], cw);
        atomicAdd(&b[9], sx);   atomicAdd(&b[10], sy);  atomicAdd(&b[11], sz);  atomicAdd(&b[12], sw);
    }
    __syncthreads();
    if (tid < NCL * 13) atomicAdd(&g_stats[tid], sh[tid]);
}

// ---------------- kernel 3: finalize cluster means ----------------
__global__ void k_final() {
    int tid = threadIdx.x;
    if (tid < NCL * 4) {
        int c = tid >> 2, i = tid & 3;
        float cnt = g_stats[c * 13];
        g_cmean_amp[tid] = g_stats[c * 13 + 1 + i] / fmaxf(cnt, 1.f);
        g_cmean_ph[tid]  = atan2f(g_stats[c * 13 + 9 + i], g_stats[c * 13 + 5 + i]);
        if (i == 0) g_ccnt[c] = cnt;
    }
}

// ---------------- kernel 4: spatial message passing -> per-node coefficients ----------------
__global__ void k_coeff(const float* __restrict__ off, const float* __restrict__ tr,
                        const float4* __restrict__ amp4, const float4* __restrict__ ph4,
                        const float* __restrict__ lw, const float* __restrict__ rw,
                        const int* __restrict__ lidx, const int* __restrict__ ridx,
                        const int* __restrict__ labels) {
    int n = blockIdx.x * blockDim.x + threadIdx.x;
    if (n >= NN) return;

    float la[4] = {0, 0, 0, 0}, lc[4] = {0, 0, 0, 0}, ls[4] = {0, 0, 0, 0};
#pragma unroll
    for (int k = 0; k < 5; k++) {
        int   j = __ldg(&lidx[n * 5 + k]);
        float w = __ldg(&lw[n * 5 + k]);
        float4 a = __ldg(&amp4[j]);
        float4 c = g_cosph[j];
        float4 s = g_sinph[j];
        la[0] = fmaf(a.x, w, la[0]); la[1] = fmaf(a.y, w, la[1]); la[2] = fmaf(a.z, w, la[2]); la[3] = fmaf(a.w, w, la[3]);
        lc[0] = fmaf(c.x, w, lc[0]); lc[1] = fmaf(c.y, w, lc[1]); lc[2] = fmaf(c.z, w, lc[2]); lc[3] = fmaf(c.w, w, lc[3]);
        ls[0] = fmaf(s.x, w, ls[0]); ls[1] = fmaf(s.y, w, ls[1]); ls[2] = fmaf(s.z, w, ls[2]); ls[3] = fmaf(s.w, w, ls[3]);
    }
    float ra[4] = {0, 0, 0, 0}, rc[4] = {0, 0, 0, 0}, rs[4] = {0, 0, 0, 0};
#pragma unroll
    for (int k = 0; k < 15; k++) {
        int   j = __ldg(&ridx[n * 15 + k]);
        float w = __ldg(&rw[n * 15 + k]);
        float4 a = __ldg(&amp4[j]);
        float4 c = g_cosph[j];
        float4 s = g_sinph[j];
        ra[0] = fmaf(a.x, w, ra[0]); ra[1] = fmaf(a.y, w, ra[1]); ra[2] = fmaf(a.z, w, ra[2]); ra[3] = fmaf(a.w, w, ra[3]);
        rc[0] = fmaf(c.x, w, rc[0]); rc[1] = fmaf(c.y, w, rc[1]); rc[2] = fmaf(c.z, w, rc[2]); rc[3] = fmaf(c.w, w, rc[3]);
        rs[0] = fmaf(s.x, w, rs[0]); rs[1] = fmaf(s.y, w, rs[1]); rs[2] = fmaf(s.z, w, rs[2]); rs[3] = fmaf(s.w, w, rs[3]);
    }

    int   l   = labels[n];
    float cnt = g_ccnt[l];
    bool  big = cnt > 1.f;
    float4 pav = __ldg(&amp4[n]);
    float4 ppv = __ldg(&ph4[n]);
    float pa[4] = {pav.x, pav.y, pav.z, pav.w};
    float pp[4] = {ppv.x, ppv.y, ppv.z, ppv.w};

    float cbuf[12];
    cbuf[0] = off[n];
    cbuf[1] = tr[n];
#pragma unroll
    for (int i = 0; i < 4; i++) {
        // amplitude path (linear means)
        float cluA  = big ? g_cmean_amp[l * 4 + i] : pa[i];
        float combA = 0.5f * la[i] + 0.3f * (0.7f * ra[i]) + 0.2f * cluA;
        float amp   = 0.7f * pa[i] + 0.3f * combA;
        // phase path (circular means -> angles, then linear blend per reference)
        float lp    = atan2f(ls[i], lc[i]);
        float rp    = atan2f(rs[i], rc[i]);
        float cluP  = big ? g_cmean_ph[l * 4 + i] : pp[i];
        float combP = 0.5f * lp + 0.3f * rp + 0.2f * cluP;
        float ph    = 0.7f * pp[i] + 0.3f * combP;
        float sv, cv;
        sincosf(ph, &sv, &cv);
        cbuf[2 + 2 * i] = amp * cv;   // multiplies sin(w t) basis
        cbuf[3 + 2 * i] = amp * sv;   // multiplies cos(w t) basis
    }
    cbuf[10] = 0.f;
    cbuf[11] = 0.f;
    float4* co4 = reinterpret_cast<float4*>(g_coeff + (size_t)n * 12);
    co4[0] = make_float4(cbuf[0], cbuf[1], cbuf[2], cbuf[3]);
    co4[1] = make_float4(cbuf[4], cbuf[5], cbuf[6], cbuf[7]);
    co4[2] = make_float4(cbuf[8], cbuf[9], cbuf[10], cbuf[11]);
}

// ---------------- kernel 5: basis table over t ----------------
__global__ void k_basis(const float* __restrict__ tv) {
    int t = blockIdx.x * blockDim.x + threadIdx.x;
    if (t >= TT) return;
    float x = tv[t];
    g_basis[0 * 1024 + t] = 1.f;
    g_basis[1 * 1024 + t] = x;
    const float freqs[4] = {4.f, 2.f, 1.f, 0.5f};  // 1/period
#pragma unroll
    for (int i = 0; i < 4; i++) {
        float th = TWO_PI_F * freqs[i] * x;
        float s, c;
        sincosf(th, &s, &c);
        g_basis[(2 + 2 * i) * 1024 + t] = s;
        g_basis[(3 + 2 * i) * 1024 + t] = c;
    }
}

// ---------------- kernel 6: out[n,t] = sum_j coeff[n,j] * basis[j,t] ----------------
#define ROWS_PER_BLK 125

__global__ void __launch_bounds__(256) k_main(float* __restrict__ out) {
    int tid = threadIdx.x;
    if (tid >= 250) return;      // 250 threads x 4 cols = T=1000
    int c0 = tid * 4;

    // basis for this thread's 4 columns, held in registers as f32x2 pairs
    unsigned long long b01[10], b23[10];
#pragma unroll
    for (int j = 0; j < 10; j++) {
        const float* bp = &g_basis[j * 1024 + c0];
        b01[j] = *reinterpret_cast<const unsigned long long*>(bp);
        b23[j] = *reinterpret_cast<const unsigned long long*>(bp + 2);
    }

    int r0 = blockIdx.x * ROWS_PER_BLK;
    int r1 = r0 + ROWS_PER_BLK;
    if (r1 > NN) r1 = NN;
    for (int r = r0; r < r1; ++r) {
        const float4* cf = reinterpret_cast<const float4*>(g_coeff + (size_t)r * 12);
        float4 q0 = __ldg(cf + 0);
        float4 q1 = __ldg(cf + 1);
        float4 q2 = __ldg(cf + 2);
        unsigned long long cd[10];
        cd[0] = pk2(q0.x, q0.x); cd[1] = pk2(q0.y, q0.y);
        cd[2] = pk2(q0.z, q0.z); cd[3] = pk2(q0.w, q0.w);
        cd[4] = pk2(q1.x, q1.x); cd[5] = pk2(q1.y, q1.y);
        cd[6] = pk2(q1.z, q1.z); cd[7] = pk2(q1.w, q1.w);
        cd[8] = pk2(q2.x, q2.x); cd[9] = pk2(q2.y, q2.y);

        unsigned long long a01 = 0ull, a23 = 0ull;  // bit pattern of (+0.f, +0.f)
#pragma unroll
        for (int j = 0; j < 10; j++) {
            a01 = f32x2_fma(cd[j], b01[j], a01);
            a23 = f32x2_fma(cd[j], b23[j], a23);
        }
        uint2 u01 = *reinterpret_cast<uint2*>(&a01);
        uint2 u23 = *reinterpret_cast<uint2*>(&a23);
        float4 o = make_float4(__uint_as_float(u01.x), __uint_as_float(u01.y),
                               __uint_as_float(u23.x), __uint_as_float(u23.y));
        *reinterpret_cast<float4*>(out + (size_t)r * TT + c0) = o;
    }
}

// ---------------- launch ----------------
extern "C" void kernel_launch(void* const* d_in, const int* in_sizes, int n_in,
                              void* d_out, int out_size) {
    const float*  tv     = (const float*)d_in[0];   // time_vector [T]
    const float*  off    = (const float*)d_in[1];   // constant_offset [N]
    const float*  tr     = (const float*)d_in[2];   // linear_trend [N]
    const float4* amp4   = (const float4*)d_in[3];  // seasonal_amplitudes [N,4]
    const float4* ph4    = (const float4*)d_in[4];  // seasonal_phases [N,4]
    const float*  lw     = (const float*)d_in[5];   // local_w [N,5]
    const float*  rw     = (const float*)d_in[6];   // regional_w [N,15]
    const int*    lidx   = (const int*)d_in[7];     // local_idx [N,5]
    const int*    ridx   = (const int*)d_in[8];     // regional_idx [N,15]
    const int*    labels = (const int*)d_in[9];     // cluster_labels [N]
    float* out = (float*)d_out;

    int nblk = (NN + 255) / 256;
    k_zero<<<1, 96>>>();
    k_accum<<<nblk, 256>>>(amp4, ph4, labels);
    k_final<<<1, 32>>>();
    k_coeff<<<nblk, 256>>>(off, tr, amp4, ph4, lw, rw, lidx, ridx, labels);
    k_basis<<<(TT + 255) / 256, 256>>>(tv);
    k_main<<<(NN + ROWS_PER_BLK - 1) / ROWS_PER_BLK, 256>>>(out);
}